// round 10
// baseline (speedup 1.0000x reference)
#include <cuda_runtime.h>
#include <cuda_bf16.h>
#include <math.h>
#include <stdint.h>

#define TT    4096      // BATCH * SEQ tokens
#define HID   4096
#define NH    32
#define NKV   8
#define HD    128
#define QKVD  6144      // (32 + 16) * 128
#define SEQ   1024
#define NB    4

// Scratch (static device globals; no runtime allocation)
__device__ float g_qkv[(size_t)TT * QKVD];   // 96 MB
// pre-split bf16 operand buffers
__device__ __nv_bfloat16 g_hshi[(size_t)TT * HID];
__device__ __nv_bfloat16 g_hslo[(size_t)TT * HID];
__device__ __nv_bfloat16 g_wqhi[(size_t)QKVD * HID];
__device__ __nv_bfloat16 g_wqlo[(size_t)QKVD * HID];
__device__ __nv_bfloat16 g_wohi[(size_t)HID * HID];
__device__ __nv_bfloat16 g_wolo[(size_t)HID * HID];
__device__ __nv_bfloat16 g_atthi[(size_t)TT * HID];
__device__ __nv_bfloat16 g_attlo[(size_t)TT * HID];
// split bf16 q/k/v (head-major)
__device__ __nv_bfloat16 g_qhi[(size_t)NB * NH * SEQ * HD];
__device__ __nv_bfloat16 g_qlo[(size_t)NB * NH * SEQ * HD];
__device__ __nv_bfloat16 g_khi[(size_t)NB * NKV * SEQ * HD];
__device__ __nv_bfloat16 g_klo[(size_t)NB * NKV * SEQ * HD];
__device__ __nv_bfloat16 g_vhi[(size_t)NB * NKV * SEQ * HD];
__device__ __nv_bfloat16 g_vlo[(size_t)NB * NKV * SEQ * HD];

// ===========================================================================
// helpers
// ===========================================================================
__device__ __forceinline__ uint32_t smem_u32(const void* p) {
    uint32_t a;
    asm("{ .reg .u64 t; cvta.to.shared.u64 t, %1; cvt.u32.u64 %0, t; }"
        : "=r"(a) : "l"(p));
    return a;
}
__device__ __forceinline__ void ldsm_x4(uint32_t* r, uint32_t addr) {
    asm volatile("ldmatrix.sync.aligned.m8n8.x4.shared.b16 {%0,%1,%2,%3}, [%4];"
                 : "=r"(r[0]), "=r"(r[1]), "=r"(r[2]), "=r"(r[3]) : "r"(addr));
}
__device__ __forceinline__ void ldsm_x4_t(uint32_t* r, uint32_t addr) {
    asm volatile("ldmatrix.sync.aligned.m8n8.x4.trans.shared.b16 {%0,%1,%2,%3}, [%4];"
                 : "=r"(r[0]), "=r"(r[1]), "=r"(r[2]), "=r"(r[3]) : "r"(addr));
}
__device__ __forceinline__ void mma_bf16(float* c, const uint32_t* a,
                                         uint32_t b0, uint32_t b1) {
    asm volatile(
        "mma.sync.aligned.m16n8k16.row.col.f32.bf16.bf16.f32 "
        "{%0,%1,%2,%3}, {%4,%5,%6,%7}, {%8,%9}, {%0,%1,%2,%3};"
        : "+f"(c[0]), "+f"(c[1]), "+f"(c[2]), "+f"(c[3])
        : "r"(a[0]), "r"(a[1]), "r"(a[2]), "r"(a[3]), "r"(b0), "r"(b1));
}
__device__ __forceinline__ void cp16(uint32_t dst, const void* src) {
    asm volatile("cp.async.cg.shared.global [%0], [%1], 16;" :: "r"(dst), "l"(src));
}
#define CP_COMMIT() asm volatile("cp.async.commit_group;" ::: "memory")
#define CP_WAIT0()  asm volatile("cp.async.wait_group 0;" ::: "memory")
#define CP_WAIT1()  asm volatile("cp.async.wait_group 1;" ::: "memory")

// split 4 fp32 -> packed hi bf16x2 pair + lo bf16x2 pair
__device__ __forceinline__ void split4(float4 f, uint32_t* hi, uint32_t* lo) {
    uint32_t x0 = __float_as_uint(f.x), x1 = __float_as_uint(f.y);
    uint32_t x2 = __float_as_uint(f.z), x3 = __float_as_uint(f.w);
    hi[0] = __byte_perm(x0, x1, 0x7632);
    hi[1] = __byte_perm(x2, x3, 0x7632);
    float l0 = f.x - __uint_as_float(x0 & 0xFFFF0000u);
    float l1 = f.y - __uint_as_float(x1 & 0xFFFF0000u);
    float l2 = f.z - __uint_as_float(x2 & 0xFFFF0000u);
    float l3 = f.w - __uint_as_float(x3 & 0xFFFF0000u);
    __nv_bfloat162 b0 = __floats2bfloat162_rn(l0, l1);
    __nv_bfloat162 b1 = __floats2bfloat162_rn(l2, l3);
    lo[0] = *reinterpret_cast<uint32_t*>(&b0);
    lo[1] = *reinterpret_cast<uint32_t*>(&b1);
}

// ===========================================================================
// split2: fp32 buffer -> bf16 hi/lo buffers.  8 elements per thread.
// ===========================================================================
__global__ __launch_bounds__(256) void split2(const float* __restrict__ src,
                                              __nv_bfloat16* __restrict__ hi,
                                              __nv_bfloat16* __restrict__ lo,
                                              int n8) {
    int i = blockIdx.x * 256 + threadIdx.x;
    if (i >= n8) return;
    const float4* s = reinterpret_cast<const float4*>(src) + (size_t)i * 2;
    float4 f0 = s[0], f1 = s[1];
    uint32_t h0[2], l0[2], h1[2], l1[2];
    split4(f0, h0, l0);
    split4(f1, h1, l1);
    *reinterpret_cast<uint4*>(hi + (size_t)i * 8) = make_uint4(h0[0], h0[1], h1[0], h1[1]);
    *reinterpret_cast<uint4*>(lo + (size_t)i * 8) = make_uint4(l0[0], l0[1], l1[0], l1[1]);
}

// ===========================================================================
// gemm_big (NT): C = (Ahi+Alo) @ (Bhi+Blo)^T, bf16 in, fp32 out.
// 3 products: hi*hi + hi*lo + lo*hi.
// CTA tile 128x256, 8 warps (2Mx4N), warp tile 64x64, BK=32, 2-stage cp.async.
// A-fragments (hi+lo, 4 m16 tiles) loaded once per k16 and reused over all
// 8 n-tiles -> 85 B smem traffic per MMA (vs 128 at 32x64).
// ===========================================================================
#define GBM 128
#define GBN 256
#define GKB 32
#define GSTR 40                          // element stride (80B row)
#define ATILEB (128 * GSTR * 2)          // 10240 B
#define BTILEB (256 * GSTR * 2)          // 20480 B
#define GSTAGEB (2 * ATILEB + 2 * BTILEB)   // 61440 B
#define GEMM_SMEM (2 * GSTAGEB)          // 122880 B

__global__ __launch_bounds__(256, 1) void gemm_big(
        const __nv_bfloat16* __restrict__ Ahi, const __nv_bfloat16* __restrict__ Alo,
        const __nv_bfloat16* __restrict__ Bhi, const __nv_bfloat16* __restrict__ Blo,
        float* __restrict__ C, int M, int N, int K) {
    extern __shared__ char sm8[];
    const uint32_t sb = smem_u32(sm8);
    const int tid = threadIdx.x;
    const int wid = tid >> 5;
    const int lane = tid & 31;
    const int wm = wid & 1;          // m offset 64*wm
    const int wn = wid >> 1;         // n offset 64*wn
    const int bm = blockIdx.y * GBM;
    const int bn = blockIdx.x * GBN;

    float acc[4][8][4];
#pragma unroll
    for (int i = 0; i < 4; i++)
#pragma unroll
        for (int j = 0; j < 8; j++)
#pragma unroll
            for (int q = 0; q < 4; q++) acc[i][j][q] = 0.f;

    // smem stage layout: Ahi | Alo | Bhi | Blo
    // ldsm fragment base offsets (bytes)
    const uint32_t aOffB = ((wm * 64 + (lane & 15)) * GSTR + (lane >> 4) * 8) * 2;
    const uint32_t bOffB = ((wn * 64 + (lane & 7) + ((lane >> 4) & 1) * 8) * GSTR
                           + ((lane >> 3) & 1) * 8) * 2;

    // cp.async: BK=32 -> 4 16B-chunks per row.  A: 512 chunks, B: 1024 chunks.
    const int ar = tid >> 2, ac = tid & 3;        // A rows tid>>2 (+64)
    const int br = tid >> 2, bc = tid & 3;        // B rows tid>>2 (+64,128,192)

    auto load_stage = [&](uint32_t base, int k0) {
#pragma unroll
        for (int u = 0; u < 2; ++u) {
            int row = ar + u * 64;
            uint32_t d = base + row * (GSTR * 2) + ac * 16;
            size_t ao = (size_t)(bm + row) * K + k0 + ac * 8;
            cp16(d, Ahi + ao);
            cp16(d + ATILEB, Alo + ao);
        }
#pragma unroll
        for (int u = 0; u < 4; ++u) {
            int row = br + u * 64;
            uint32_t d = base + 2 * ATILEB + row * (GSTR * 2) + bc * 16;
            size_t bo = (size_t)(bn + row) * K + k0 + bc * 8;
            cp16(d, Bhi + bo);
            cp16(d + BTILEB, Blo + bo);
        }
    };

    const int NC = K / GKB;

    load_stage(sb, 0);
    CP_COMMIT();

    for (int kc = 0; kc < NC; ++kc) {
        if (kc + 1 < NC) {
            load_stage(sb + ((kc + 1) & 1) * GSTAGEB, (kc + 1) * GKB);
            CP_COMMIT();
            CP_WAIT1();
        } else {
            CP_WAIT0();
        }
        __syncthreads();

        const uint32_t base = sb + (kc & 1) * GSTAGEB;
#pragma unroll
        for (int ks = 0; ks < 2; ++ks) {
            const uint32_t ko = ks * 32;
            // A fragments: 4 m16 tiles, hi + lo (reused across all 8 n-tiles)
            uint32_t ah[4][4], al[4][4];
#pragma unroll
            for (int mt = 0; mt < 4; ++mt) {
                uint32_t aa = base + aOffB + mt * (16 * GSTR * 2) + ko;
                ldsm_x4(ah[mt], aa);
                ldsm_x4(al[mt], aa + ATILEB);
            }
#pragma unroll
            for (int p = 0; p < 4; ++p) {
                uint32_t bh[4], bl[4];
                uint32_t ba = base + 2 * ATILEB + bOffB + p * (16 * GSTR * 2) + ko;
                ldsm_x4(bh, ba);
                ldsm_x4(bl, ba + BTILEB);
#pragma unroll
                for (int n2 = 0; n2 < 2; ++n2) {
                    const int nt = p * 2 + n2;
                    uint32_t h0 = bh[n2 * 2], h1 = bh[n2 * 2 + 1];
                    uint32_t l0 = bl[n2 * 2], l1 = bl[n2 * 2 + 1];
#pragma unroll
                    for (int mt = 0; mt < 4; ++mt) {
                        mma_bf16(acc[mt][nt], ah[mt], h0, h1);
                        mma_bf16(acc[mt][nt], ah[mt], l0, l1);
                        mma_bf16(acc[mt][nt], al[mt], h0, h1);
                    }
                }
            }
        }
        __syncthreads();
    }

    const int g = lane >> 2;
    const int cc = (lane & 3) * 2;
#pragma unroll
    for (int mt = 0; mt < 4; ++mt) {
        int rowc = bm + wm * 64 + mt * 16 + g;
#pragma unroll
        for (int nt = 0; nt < 8; ++nt) {
            int col = bn + wn * 64 + nt * 8 + cc;
            *reinterpret_cast<float2*>(&C[(size_t)rowc * N + col]) =
                make_float2(acc[mt][nt][0], acc[mt][nt][1]);
            *reinterpret_cast<float2*>(&C[(size_t)(rowc + 8) * N + col]) =
                make_float2(acc[mt][nt][2], acc[mt][nt][3]);
        }
    }
}

// ===========================================================================
// fused RoPE + head-major split to bf16 hi/lo.  Q gets 1/sqrt(128) folded in.
// ===========================================================================
__global__ __launch_bounds__(256) void rope_split(const float* __restrict__ qkv,
        __nv_bfloat16* __restrict__ qhi, __nv_bfloat16* __restrict__ qlo,
        __nv_bfloat16* __restrict__ khi, __nv_bfloat16* __restrict__ klo,
        __nv_bfloat16* __restrict__ vhi, __nv_bfloat16* __restrict__ vlo) {
    int x = blockIdx.x * 256 + threadIdx.x;
    int i = x & 63;
    int r = x >> 6;
    int hh = r % (NH + 2 * NKV);
    int t = r / (NH + 2 * NKV);
    int b = t >> 10;
    int s = t & (SEQ - 1);

    const float* base = qkv + (size_t)t * QKVD + hh * HD;
    float x1 = base[i];
    float x2 = base[i + 64];
    float y1, y2;
    if (hh < NH + NKV) {
        float invf = 1.0f / powf(10000.0f, (float)(2 * i) * (1.0f / (float)HD));
        float ang = (float)s * invf;
        float sn, cs;
        sincosf(ang, &sn, &cs);
        y1 = x1 * cs - x2 * sn;
        y2 = x2 * cs + x1 * sn;
    } else { y1 = x1; y2 = x2; }

    __nv_bfloat16 *dh, *dl;
    size_t off;
    if (hh < NH) {
        const float sc = 0.08838834764831845f;
        y1 *= sc; y2 *= sc;
        off = ((size_t)(b * NH + hh) * SEQ + s) * HD;
        dh = qhi; dl = qlo;
    } else if (hh < NH + NKV) {
        off = ((size_t)(b * NKV + (hh - NH)) * SEQ + s) * HD;
        dh = khi; dl = klo;
    } else {
        off = ((size_t)(b * NKV + (hh - NH - NKV)) * SEQ + s) * HD;
        dh = vhi; dl = vlo;
    }
    uint32_t u1 = __float_as_uint(y1), u2 = __float_as_uint(y2);
    float h1 = __uint_as_float(u1 & 0xFFFF0000u);
    float h2 = __uint_as_float(u2 & 0xFFFF0000u);
    dh[off + i]      = __float2bfloat16(h1);
    dh[off + i + 64] = __float2bfloat16(h2);
    dl[off + i]      = __float2bfloat16(y1 - h1);
    dl[off + i + 64] = __float2bfloat16(y2 - h2);
}

// ===========================================================================
// Tensor-core causal GQA flash attention (bf16x3 split).
// Epilogue writes split bf16 hi/lo directly (feeds O-proj GEMM).
// ===========================================================================
#define AQ   128
#define AKT  64
#define ASTR 136
#define Q_BYTES   (AQ * ASTR * 2)
#define KV_BYTES  (AKT * ASTR * 2)
#define KVBUF     (4 * KV_BYTES)
#define ATT_SMEM  (2 * Q_BYTES + 2 * KVBUF)

__global__ __launch_bounds__(256) void attn_mma(
        const __nv_bfloat16* __restrict__ Qhi, const __nv_bfloat16* __restrict__ Qlo,
        const __nv_bfloat16* __restrict__ Khi, const __nv_bfloat16* __restrict__ Klo,
        const __nv_bfloat16* __restrict__ Vhi, const __nv_bfloat16* __restrict__ Vlo,
        __nv_bfloat16* __restrict__ Ohi, __nv_bfloat16* __restrict__ Olo) {
    extern __shared__ char sm8[];
    const uint32_t sb = smem_u32(sm8);
    const int tid = threadIdx.x, wid = tid >> 5, lane = tid & 31;
    const int qtile = gridDim.x - 1 - blockIdx.x;
    const int h = blockIdx.y, b = blockIdx.z;
    const int kvh = h >> 2;

    const size_t qbase = ((size_t)(b * NH + h) * SEQ + qtile * AQ) * HD;
    const size_t kbase = ((size_t)(b * NKV + kvh) * SEQ) * HD;

    for (int i = tid; i < AQ * 16; i += 256) {
        int row = i >> 4, c = i & 15;
        uint32_t d = sb + row * (ASTR * 2) + c * 16;
        const size_t src = qbase + (size_t)row * HD + c * 8;
        cp16(d, Qhi + src);
        cp16(d + Q_BYTES, Qlo + src);
    }
    {
        uint32_t dst0 = sb + 2 * Q_BYTES;
        for (int i = tid; i < AKT * 16; i += 256) {
            int row = i >> 4, c = i & 15;
            uint32_t d = dst0 + row * (ASTR * 2) + c * 16;
            const size_t src = kbase + (size_t)row * HD + c * 8;
            cp16(d,                Khi + src);
            cp16(d + KV_BYTES,     Klo + src);
            cp16(d + 2 * KV_BYTES, Vhi + src);
            cp16(d + 3 * KV_BYTES, Vlo + src);
        }
    }
    CP_COMMIT();

    float oacc[16][4];
#pragma unroll
    for (int n = 0; n < 16; n++)
#pragma unroll
        for (int q = 0; q < 4; q++) oacc[n][q] = 0.f;
    float m0 = -1e30f, m1 = -1e30f, l0 = 0.f, l1 = 0.f;

    const uint32_t aRow = wid * 16 + (lane & 15);
    const uint32_t aColP = (lane >> 4) * 8;
    const uint32_t qAddr = sb + (aRow * ASTR + aColP) * 2;
    const uint32_t bRowP = (lane & 7) + ((lane >> 4) & 1) * 8;
    const uint32_t bColP = ((lane >> 3) & 1) * 8;
    const uint32_t vRowP = (lane & 7) + ((lane >> 3) & 1) * 8;
    const uint32_t vColP = (lane >> 4) * 8;

    const int nkt = 2 * qtile + 2;
    const int row0g = qtile * AQ + wid * 16 + (lane >> 2);

    for (int kt = 0; kt < nkt; ++kt) {
        const int s = kt & 1;
        CP_WAIT0();
        __syncthreads();
        if (kt + 1 < nkt) {
            uint32_t dst0 = sb + 2 * Q_BYTES + (s ^ 1) * KVBUF;
            const size_t kvoff = kbase + (size_t)(kt + 1) * AKT * HD;
            for (int i = tid; i < AKT * 16; i += 256) {
                int row = i >> 4, c = i & 15;
                uint32_t d = dst0 + row * (ASTR * 2) + c * 16;
                const size_t src = kvoff + (size_t)row * HD + c * 8;
                cp16(d,                Khi + src);
                cp16(d + KV_BYTES,     Klo + src);
                cp16(d + 2 * KV_BYTES, Vhi + src);
                cp16(d + 3 * KV_BYTES, Vlo + src);
            }
            CP_COMMIT();
        }

        const uint32_t kvb = sb + 2 * Q_BYTES + s * KVBUF;

        float sacc[8][4];
#pragma unroll
        for (int n = 0; n < 8; n++)
#pragma unroll
            for (int q = 0; q < 4; q++) sacc[n][q] = 0.f;

#pragma unroll
        for (int ks = 0; ks < 8; ++ks) {
            uint32_t aq[4], aql[4];
            uint32_t qa = qAddr + ks * 32;
            ldsm_x4(aq, qa);
            ldsm_x4(aql, qa + Q_BYTES);
            uint32_t bh[4][4], bl[4][4];
#pragma unroll
            for (int p = 0; p < 4; ++p) {
                uint32_t ba = kvb + ((p * 16 + bRowP) * ASTR + ks * 16 + bColP) * 2;
                ldsm_x4(bh[p], ba);
                ldsm_x4(bl[p], ba + KV_BYTES);
            }
#pragma unroll
            for (int nt = 0; nt < 8; ++nt) {
                uint32_t h0 = bh[nt >> 1][(nt & 1) * 2];
                uint32_t h1 = bh[nt >> 1][(nt & 1) * 2 + 1];
                uint32_t q0 = bl[nt >> 1][(nt & 1) * 2];
                uint32_t q1 = bl[nt >> 1][(nt & 1) * 2 + 1];
                mma_bf16(sacc[nt], aq, h0, h1);
                mma_bf16(sacc[nt], aq, q0, q1);
                mma_bf16(sacc[nt], aql, h0, h1);
            }
        }

        if (kt * AKT + AKT - 1 > qtile * AQ + wid * 16) {
            const int colb = kt * AKT + (lane & 3) * 2;
#pragma unroll
            for (int nt = 0; nt < 8; ++nt) {
                int c0 = colb + nt * 8;
                if (c0 > row0g)         sacc[nt][0] = -1e30f;
                if (c0 + 1 > row0g)     sacc[nt][1] = -1e30f;
                if (c0 > row0g + 8)     sacc[nt][2] = -1e30f;
                if (c0 + 1 > row0g + 8) sacc[nt][3] = -1e30f;
            }
        }

        float mx0 = -1e30f, mx1 = -1e30f;
#pragma unroll
        for (int nt = 0; nt < 8; ++nt) {
            mx0 = fmaxf(mx0, fmaxf(sacc[nt][0], sacc[nt][1]));
            mx1 = fmaxf(mx1, fmaxf(sacc[nt][2], sacc[nt][3]));
        }
        mx0 = fmaxf(mx0, __shfl_xor_sync(0xffffffffu, mx0, 1));
        mx0 = fmaxf(mx0, __shfl_xor_sync(0xffffffffu, mx0, 2));
        mx1 = fmaxf(mx1, __shfl_xor_sync(0xffffffffu, mx1, 1));
        mx1 = fmaxf(mx1, __shfl_xor_sync(0xffffffffu, mx1, 2));
        float nm0 = fmaxf(m0, mx0), nm1 = fmaxf(m1, mx1);
        float r0 = 0.f, r1 = 0.f;
#pragma unroll
        for (int nt = 0; nt < 8; ++nt) {
            sacc[nt][0] = __expf(sacc[nt][0] - nm0);
            sacc[nt][1] = __expf(sacc[nt][1] - nm0);
            sacc[nt][2] = __expf(sacc[nt][2] - nm1);
            sacc[nt][3] = __expf(sacc[nt][3] - nm1);
            r0 += sacc[nt][0] + sacc[nt][1];
            r1 += sacc[nt][2] + sacc[nt][3];
        }
        r0 += __shfl_xor_sync(0xffffffffu, r0, 1);
        r0 += __shfl_xor_sync(0xffffffffu, r0, 2);
        r1 += __shfl_xor_sync(0xffffffffu, r1, 1);
        r1 += __shfl_xor_sync(0xffffffffu, r1, 2);
        float a0 = __expf(m0 - nm0), a1 = __expf(m1 - nm1);
        l0 = l0 * a0 + r0;
        l1 = l1 * a1 + r1;
        m0 = nm0; m1 = nm1;
#pragma unroll
        for (int n = 0; n < 16; ++n) {
            oacc[n][0] *= a0; oacc[n][1] *= a0;
            oacc[n][2] *= a1; oacc[n][3] *= a1;
        }

        uint32_t ph[8][2], pl[8][2];
#pragma unroll
        for (int nt = 0; nt < 8; ++nt) {
            uint32_t u0 = __float_as_uint(sacc[nt][0]);
            uint32_t u1 = __float_as_uint(sacc[nt][1]);
            uint32_t u2 = __float_as_uint(sacc[nt][2]);
            uint32_t u3 = __float_as_uint(sacc[nt][3]);
            ph[nt][0] = __byte_perm(u0, u1, 0x7632);
            ph[nt][1] = __byte_perm(u2, u3, 0x7632);
            float e0 = sacc[nt][0] - __uint_as_float(u0 & 0xFFFF0000u);
            float e1 = sacc[nt][1] - __uint_as_float(u1 & 0xFFFF0000u);
            float e2 = sacc[nt][2] - __uint_as_float(u2 & 0xFFFF0000u);
            float e3 = sacc[nt][3] - __uint_as_float(u3 & 0xFFFF0000u);
            __nv_bfloat162 p01 = __floats2bfloat162_rn(e0, e1);
            __nv_bfloat162 p23 = __floats2bfloat162_rn(e2, e3);
            pl[nt][0] = *reinterpret_cast<uint32_t*>(&p01);
            pl[nt][1] = *reinterpret_cast<uint32_t*>(&p23);
        }

        const uint32_t vbase = kvb + 2 * KV_BYTES;
#pragma unroll
        for (int kk = 0; kk < 4; ++kk) {
            uint32_t pa[4]  = { ph[2 * kk][0], ph[2 * kk][1], ph[2 * kk + 1][0], ph[2 * kk + 1][1] };
            uint32_t pal[4] = { pl[2 * kk][0], pl[2 * kk][1], pl[2 * kk + 1][0], pl[2 * kk + 1][1] };
#pragma unroll
            for (int nt = 0; nt < 8; ++nt) {
                uint32_t va = vbase + ((kk * 16 + vRowP) * ASTR + nt * 16 + vColP) * 2;
                uint32_t vh[4], vl[4];
                ldsm_x4_t(vh, va);
                ldsm_x4_t(vl, va + KV_BYTES);
                mma_bf16(oacc[2 * nt],     pa,  vh[0], vh[1]);
                mma_bf16(oacc[2 * nt],     pa,  vl[0], vl[1]);
                mma_bf16(oacc[2 * nt],     pal, vh[0], vh[1]);
                mma_bf16(oacc[2 * nt + 1], pa,  vh[2], vh[3]);
                mma_bf16(oacc[2 * nt + 1], pa,  vl[2], vl[3]);
                mma_bf16(oacc[2 * nt + 1], pal, vh[2], vh[3]);
            }
        }
    }

    // ---- epilogue: normalize + split to bf16 hi/lo ----
    float inv0 = 1.0f / l0, inv1 = 1.0f / l1;
    const int trow = b * SEQ + row0g;
    const int cc = (lane & 3) * 2;
#pragma unroll
    for (int nt = 0; nt < 16; ++nt) {
        int col = h * HD + nt * 8 + cc;
        float o0 = oacc[nt][0] * inv0, o1 = oacc[nt][1] * inv0;
        float o2 = oacc[nt][2] * inv1, o3 = oacc[nt][3] * inv1;
        uint32_t u0 = __float_as_uint(o0), u1 = __float_as_uint(o1);
        uint32_t u2 = __float_as_uint(o2), u3 = __float_as_uint(o3);
        uint32_t hi01 = __byte_perm(u0, u1, 0x7632);
        uint32_t hi23 = __byte_perm(u2, u3, 0x7632);
        __nv_bfloat162 lo01 = __floats2bfloat162_rn(
            o0 - __uint_as_float(u0 & 0xFFFF0000u), o1 - __uint_as_float(u1 & 0xFFFF0000u));
        __nv_bfloat162 lo23 = __floats2bfloat162_rn(
            o2 - __uint_as_float(u2 & 0xFFFF0000u), o3 - __uint_as_float(u3 & 0xFFFF0000u));
        *reinterpret_cast<uint32_t*>(&Ohi[(size_t)trow * HID + col]) = hi01;
        *reinterpret_cast<uint32_t*>(&Olo[(size_t)trow * HID + col]) =
            *reinterpret_cast<uint32_t*>(&lo01);
        *reinterpret_cast<uint32_t*>(&Ohi[(size_t)(trow + 8) * HID + col]) = hi23;
        *reinterpret_cast<uint32_t*>(&Olo[(size_t)(trow + 8) * HID + col]) =
            *reinterpret_cast<uint32_t*>(&lo23);
    }
}

// ---------------------------------------------------------------------------
extern "C" void kernel_launch(void* const* d_in, const int* in_sizes, int n_in,
                              void* d_out, int out_size) {
    const float* hs    = (const float*)d_in[0];
    const float* w_qkv = (const float*)d_in[1];
    const float* w_o   = (const float*)d_in[2];
    float* out = (float*)d_out;

    float* qkv = nullptr;
    __nv_bfloat16 *hshi, *hslo, *wqhi, *wqlo, *wohi, *wolo, *atthi, *attlo;
    __nv_bfloat16 *qhi, *qlo, *khi, *klo, *vhi, *vlo;
    cudaGetSymbolAddress((void**)&qkv, g_qkv);
    cudaGetSymbolAddress((void**)&hshi, g_hshi);
    cudaGetSymbolAddress((void**)&hslo, g_hslo);
    cudaGetSymbolAddress((void**)&wqhi, g_wqhi);
    cudaGetSymbolAddress((void**)&wqlo, g_wqlo);
    cudaGetSymbolAddress((void**)&wohi, g_wohi);
    cudaGetSymbolAddress((void**)&wolo, g_wolo);
    cudaGetSymbolAddress((void**)&atthi, g_atthi);
    cudaGetSymbolAddress((void**)&attlo, g_attlo);
    cudaGetSymbolAddress((void**)&qhi, g_qhi);
    cudaGetSymbolAddress((void**)&qlo, g_qlo);
    cudaGetSymbolAddress((void**)&khi, g_khi);
    cudaGetSymbolAddress((void**)&klo, g_klo);
    cudaGetSymbolAddress((void**)&vhi, g_vhi);
    cudaGetSymbolAddress((void**)&vlo, g_vlo);

    cudaFuncSetAttribute(gemm_big, cudaFuncAttributeMaxDynamicSharedMemorySize, GEMM_SMEM);
    cudaFuncSetAttribute(attn_mma, cudaFuncAttributeMaxDynamicSharedMemorySize, ATT_SMEM);

    // 0) pre-split inputs and weights to bf16 hi/lo
    split2<<<(TT * HID / 8 + 255) / 256, 256>>>(hs, hshi, hslo, TT * HID / 8);
    split2<<<(QKVD * HID / 8 + 255) / 256, 256>>>(w_qkv, wqhi, wqlo, QKVD * HID / 8);
    split2<<<(HID * HID / 8 + 255) / 256, 256>>>(w_o, wohi, wolo, HID * HID / 8);

    // 1) QKV projection
    {
        dim3 grid(QKVD / GBN, TT / GBM);
        gemm_big<<<grid, 256, GEMM_SMEM>>>(hshi, hslo, wqhi, wqlo, qkv, TT, QKVD, HID);
    }
    // 2) fused RoPE + split to bf16 hi/lo (head-major)
    {
        int total = TT * (NH + 2 * NKV) * 64;
        rope_split<<<total / 256, 256>>>(qkv, qhi, qlo, khi, klo, vhi, vlo);
    }
    // 3) tensor-core causal GQA attention -> split bf16 output
    {
        dim3 grid(SEQ / AQ, NH, NB);
        attn_mma<<<grid, 256, ATT_SMEM>>>(qhi, qlo, khi, klo, vhi, vlo, atthi, attlo);
    }
    // 4) output projection
    {
        dim3 grid(HID / GBN, TT / GBM);
        gemm_big<<<grid, 256, GEMM_SMEM>>>(atthi, attlo, wohi, wolo, out, TT, HID, HID);
    }
}

// round 11
// speedup vs baseline: 1.0864x; 1.0864x over previous
#include <cuda_runtime.h>
#include <cuda_bf16.h>
#include <math.h>
#include <stdint.h>

#define TT    4096      // BATCH * SEQ tokens
#define HID   4096
#define NH    32
#define NKV   8
#define HD    128
#define QKVD  6144      // (32 + 16) * 128
#define SEQ   1024
#define NB    4

// Scratch (static device globals; no runtime allocation)
__device__ float g_qkv[(size_t)TT * QKVD];   // 96 MB
// pre-split bf16 operand buffers
__device__ __nv_bfloat16 g_hshi[(size_t)TT * HID];
__device__ __nv_bfloat16 g_hslo[(size_t)TT * HID];
__device__ __nv_bfloat16 g_wqhi[(size_t)QKVD * HID];
__device__ __nv_bfloat16 g_wqlo[(size_t)QKVD * HID];
__device__ __nv_bfloat16 g_wohi[(size_t)HID * HID];
__device__ __nv_bfloat16 g_wolo[(size_t)HID * HID];
__device__ __nv_bfloat16 g_atthi[(size_t)TT * HID];
__device__ __nv_bfloat16 g_attlo[(size_t)TT * HID];
// split bf16 q/k/v (head-major)
__device__ __nv_bfloat16 g_qhi[(size_t)NB * NH * SEQ * HD];
__device__ __nv_bfloat16 g_qlo[(size_t)NB * NH * SEQ * HD];
__device__ __nv_bfloat16 g_khi[(size_t)NB * NKV * SEQ * HD];
__device__ __nv_bfloat16 g_klo[(size_t)NB * NKV * SEQ * HD];
__device__ __nv_bfloat16 g_vhi[(size_t)NB * NKV * SEQ * HD];
__device__ __nv_bfloat16 g_vlo[(size_t)NB * NKV * SEQ * HD];

// ===========================================================================
// helpers
// ===========================================================================
__device__ __forceinline__ uint32_t smem_u32(const void* p) {
    uint32_t a;
    asm("{ .reg .u64 t; cvta.to.shared.u64 t, %1; cvt.u32.u64 %0, t; }"
        : "=r"(a) : "l"(p));
    return a;
}
__device__ __forceinline__ void ldsm_x4(uint32_t* r, uint32_t addr) {
    asm volatile("ldmatrix.sync.aligned.m8n8.x4.shared.b16 {%0,%1,%2,%3}, [%4];"
                 : "=r"(r[0]), "=r"(r[1]), "=r"(r[2]), "=r"(r[3]) : "r"(addr));
}
__device__ __forceinline__ void ldsm_x4_t(uint32_t* r, uint32_t addr) {
    asm volatile("ldmatrix.sync.aligned.m8n8.x4.trans.shared.b16 {%0,%1,%2,%3}, [%4];"
                 : "=r"(r[0]), "=r"(r[1]), "=r"(r[2]), "=r"(r[3]) : "r"(addr));
}
__device__ __forceinline__ void mma_bf16(float* c, const uint32_t* a,
                                         uint32_t b0, uint32_t b1) {
    asm volatile(
        "mma.sync.aligned.m16n8k16.row.col.f32.bf16.bf16.f32 "
        "{%0,%1,%2,%3}, {%4,%5,%6,%7}, {%8,%9}, {%0,%1,%2,%3};"
        : "+f"(c[0]), "+f"(c[1]), "+f"(c[2]), "+f"(c[3])
        : "r"(a[0]), "r"(a[1]), "r"(a[2]), "r"(a[3]), "r"(b0), "r"(b1));
}
__device__ __forceinline__ void cp16(uint32_t dst, const void* src) {
    asm volatile("cp.async.cg.shared.global [%0], [%1], 16;" :: "r"(dst), "l"(src));
}
#define CP_COMMIT() asm volatile("cp.async.commit_group;" ::: "memory")
#define CP_WAIT0()  asm volatile("cp.async.wait_group 0;" ::: "memory")
#define CP_WAIT1()  asm volatile("cp.async.wait_group 1;" ::: "memory")

// split 4 fp32 -> packed hi bf16x2 pair + lo bf16x2 pair
__device__ __forceinline__ void split4(float4 f, uint32_t* hi, uint32_t* lo) {
    uint32_t x0 = __float_as_uint(f.x), x1 = __float_as_uint(f.y);
    uint32_t x2 = __float_as_uint(f.z), x3 = __float_as_uint(f.w);
    hi[0] = __byte_perm(x0, x1, 0x7632);
    hi[1] = __byte_perm(x2, x3, 0x7632);
    float l0 = f.x - __uint_as_float(x0 & 0xFFFF0000u);
    float l1 = f.y - __uint_as_float(x1 & 0xFFFF0000u);
    float l2 = f.z - __uint_as_float(x2 & 0xFFFF0000u);
    float l3 = f.w - __uint_as_float(x3 & 0xFFFF0000u);
    __nv_bfloat162 b0 = __floats2bfloat162_rn(l0, l1);
    __nv_bfloat162 b1 = __floats2bfloat162_rn(l2, l3);
    lo[0] = *reinterpret_cast<uint32_t*>(&b0);
    lo[1] = *reinterpret_cast<uint32_t*>(&b1);
}

// ===========================================================================
// split2: fp32 buffer -> bf16 hi/lo buffers.  8 elements per thread.
// ===========================================================================
__global__ __launch_bounds__(256) void split2(const float* __restrict__ src,
                                              __nv_bfloat16* __restrict__ hi,
                                              __nv_bfloat16* __restrict__ lo,
                                              int n8) {
    int i = blockIdx.x * 256 + threadIdx.x;
    if (i >= n8) return;
    const float4* s = reinterpret_cast<const float4*>(src) + (size_t)i * 2;
    float4 f0 = s[0], f1 = s[1];
    uint32_t h0[2], l0[2], h1[2], l1[2];
    split4(f0, h0, l0);
    split4(f1, h1, l1);
    *reinterpret_cast<uint4*>(hi + (size_t)i * 8) = make_uint4(h0[0], h0[1], h1[0], h1[1]);
    *reinterpret_cast<uint4*>(lo + (size_t)i * 8) = make_uint4(l0[0], l0[1], l1[0], l1[1]);
}

// ===========================================================================
// gemm_w16b (NT): C = (Ahi+Alo) @ (Bhi+Blo)^T, bf16 in, fp32 out.
// 3 products: hi*hi + hi*lo + lo*hi.
// CTA tile 256x128, 512 threads, 16 warps (8Mx2N), warp tile 32x64 (the
// best-measured shape), BK=64, 2-stage cp.async.  4 warps per SMSP.
// ===========================================================================
#define GBM 256
#define GBN 128
#define GKB 64
#define GSTR 72                          // element stride (144B row)
#define ATILEB (256 * GSTR * 2)          // 36864 B
#define BTILEB (128 * GSTR * 2)          // 18432 B
#define GSTAGEB (2 * ATILEB + 2 * BTILEB)   // 110592 B
#define GEMM_SMEM (2 * GSTAGEB)          // 221184 B
#define GTHREADS 512

__global__ __launch_bounds__(GTHREADS, 1) void gemm_w16b(
        const __nv_bfloat16* __restrict__ Ahi, const __nv_bfloat16* __restrict__ Alo,
        const __nv_bfloat16* __restrict__ Bhi, const __nv_bfloat16* __restrict__ Blo,
        float* __restrict__ C, int M, int N, int K) {
    extern __shared__ char sm8[];
    const uint32_t sb = smem_u32(sm8);
    const int tid = threadIdx.x;
    const int wid = tid >> 5;
    const int lane = tid & 31;
    const int wm = wid & 7;          // m offset 32*wm
    const int wn = wid >> 3;         // n offset 64*wn
    const int bm = blockIdx.y * GBM;
    const int bn = blockIdx.x * GBN;

    float acc[2][8][4];
#pragma unroll
    for (int i = 0; i < 2; i++)
#pragma unroll
        for (int j = 0; j < 8; j++)
#pragma unroll
            for (int q = 0; q < 4; q++) acc[i][j][q] = 0.f;

    // smem stage layout: Ahi | Alo | Bhi | Blo
    const uint32_t aOffB = ((wm * 32 + (lane & 15)) * GSTR + (lane >> 4) * 8) * 2;
    const uint32_t bOffB = ((wn * 64 + (lane & 7) + ((lane >> 4) & 1) * 8) * GSTR
                           + ((lane >> 3) & 1) * 8) * 2;

    // cp.async: BK=64 -> 8 16B-chunks per row.  A: 2048 chunks/tensor, B: 1024.
    const int r0 = tid >> 3;             // 0..63
    const int cc0 = tid & 7;

    auto load_stage = [&](uint32_t base, int k0) {
#pragma unroll
        for (int u = 0; u < 4; ++u) {
            int row = r0 + u * 64;
            uint32_t d = base + row * (GSTR * 2) + cc0 * 16;
            size_t ao = (size_t)(bm + row) * K + k0 + cc0 * 8;
            cp16(d, Ahi + ao);
            cp16(d + ATILEB, Alo + ao);
        }
#pragma unroll
        for (int u = 0; u < 2; ++u) {
            int row = r0 + u * 64;
            uint32_t d = base + 2 * ATILEB + row * (GSTR * 2) + cc0 * 16;
            size_t bo = (size_t)(bn + row) * K + k0 + cc0 * 8;
            cp16(d, Bhi + bo);
            cp16(d + BTILEB, Blo + bo);
        }
    };

    const int NC = K / GKB;

    load_stage(sb, 0);
    CP_COMMIT();

    for (int kc = 0; kc < NC; ++kc) {
        if (kc + 1 < NC) {
            load_stage(sb + ((kc + 1) & 1) * GSTAGEB, (kc + 1) * GKB);
            CP_COMMIT();
            CP_WAIT1();
        } else {
            CP_WAIT0();
        }
        __syncthreads();

        const uint32_t base = sb + (kc & 1) * GSTAGEB;
#pragma unroll
        for (int ks = 0; ks < 4; ++ks) {
            const uint32_t ko = ks * 32;
            uint32_t ah[2][4], al[2][4];
#pragma unroll
            for (int mt = 0; mt < 2; ++mt) {
                uint32_t aa = base + aOffB + mt * (16 * GSTR * 2) + ko;
                ldsm_x4(ah[mt], aa);
                ldsm_x4(al[mt], aa + ATILEB);
            }
#pragma unroll
            for (int p = 0; p < 4; ++p) {
                uint32_t bh[4], bl[4];
                uint32_t ba = base + 2 * ATILEB + bOffB + p * (16 * GSTR * 2) + ko;
                ldsm_x4(bh, ba);
                ldsm_x4(bl, ba + BTILEB);
#pragma unroll
                for (int n2 = 0; n2 < 2; ++n2) {
                    const int nt = p * 2 + n2;
                    uint32_t h0 = bh[n2 * 2], h1 = bh[n2 * 2 + 1];
                    uint32_t l0 = bl[n2 * 2], l1 = bl[n2 * 2 + 1];
#pragma unroll
                    for (int mt = 0; mt < 2; ++mt) {
                        mma_bf16(acc[mt][nt], ah[mt], h0, h1);
                        mma_bf16(acc[mt][nt], ah[mt], l0, l1);
                        mma_bf16(acc[mt][nt], al[mt], h0, h1);
                    }
                }
            }
        }
        __syncthreads();
    }

    const int g = lane >> 2;
    const int cc = (lane & 3) * 2;
#pragma unroll
    for (int mt = 0; mt < 2; ++mt) {
        int rowc = bm + wm * 32 + mt * 16 + g;
#pragma unroll
        for (int nt = 0; nt < 8; ++nt) {
            int col = bn + wn * 64 + nt * 8 + cc;
            *reinterpret_cast<float2*>(&C[(size_t)rowc * N + col]) =
                make_float2(acc[mt][nt][0], acc[mt][nt][1]);
            *reinterpret_cast<float2*>(&C[(size_t)(rowc + 8) * N + col]) =
                make_float2(acc[mt][nt][2], acc[mt][nt][3]);
        }
    }
}

// ===========================================================================
// fused RoPE + head-major split to bf16 hi/lo.  Q gets 1/sqrt(128) folded in.
// ===========================================================================
__global__ __launch_bounds__(256) void rope_split(const float* __restrict__ qkv,
        __nv_bfloat16* __restrict__ qhi, __nv_bfloat16* __restrict__ qlo,
        __nv_bfloat16* __restrict__ khi, __nv_bfloat16* __restrict__ klo,
        __nv_bfloat16* __restrict__ vhi, __nv_bfloat16* __restrict__ vlo) {
    int x = blockIdx.x * 256 + threadIdx.x;
    int i = x & 63;
    int r = x >> 6;
    int hh = r % (NH + 2 * NKV);
    int t = r / (NH + 2 * NKV);
    int b = t >> 10;
    int s = t & (SEQ - 1);

    const float* base = qkv + (size_t)t * QKVD + hh * HD;
    float x1 = base[i];
    float x2 = base[i + 64];
    float y1, y2;
    if (hh < NH + NKV) {
        float invf = 1.0f / powf(10000.0f, (float)(2 * i) * (1.0f / (float)HD));
        float ang = (float)s * invf;
        float sn, cs;
        sincosf(ang, &sn, &cs);
        y1 = x1 * cs - x2 * sn;
        y2 = x2 * cs + x1 * sn;
    } else { y1 = x1; y2 = x2; }

    __nv_bfloat16 *dh, *dl;
    size_t off;
    if (hh < NH) {
        const float sc = 0.08838834764831845f;
        y1 *= sc; y2 *= sc;
        off = ((size_t)(b * NH + hh) * SEQ + s) * HD;
        dh = qhi; dl = qlo;
    } else if (hh < NH + NKV) {
        off = ((size_t)(b * NKV + (hh - NH)) * SEQ + s) * HD;
        dh = khi; dl = klo;
    } else {
        off = ((size_t)(b * NKV + (hh - NH - NKV)) * SEQ + s) * HD;
        dh = vhi; dl = vlo;
    }
    uint32_t u1 = __float_as_uint(y1), u2 = __float_as_uint(y2);
    float h1 = __uint_as_float(u1 & 0xFFFF0000u);
    float h2 = __uint_as_float(u2 & 0xFFFF0000u);
    dh[off + i]      = __float2bfloat16(h1);
    dh[off + i + 64] = __float2bfloat16(h2);
    dl[off + i]      = __float2bfloat16(y1 - h1);
    dl[off + i + 64] = __float2bfloat16(y2 - h2);
}

// ===========================================================================
// Tensor-core causal GQA flash attention (bf16x3 split).
// Epilogue writes split bf16 hi/lo directly (feeds O-proj GEMM).
// ===========================================================================
#define AQ   128
#define AKT  64
#define ASTR 136
#define Q_BYTES   (AQ * ASTR * 2)
#define KV_BYTES  (AKT * ASTR * 2)
#define KVBUF     (4 * KV_BYTES)
#define ATT_SMEM  (2 * Q_BYTES + 2 * KVBUF)

__global__ __launch_bounds__(256) void attn_mma(
        const __nv_bfloat16* __restrict__ Qhi, const __nv_bfloat16* __restrict__ Qlo,
        const __nv_bfloat16* __restrict__ Khi, const __nv_bfloat16* __restrict__ Klo,
        const __nv_bfloat16* __restrict__ Vhi, const __nv_bfloat16* __restrict__ Vlo,
        __nv_bfloat16* __restrict__ Ohi, __nv_bfloat16* __restrict__ Olo) {
    extern __shared__ char sm8[];
    const uint32_t sb = smem_u32(sm8);
    const int tid = threadIdx.x, wid = tid >> 5, lane = tid & 31;
    const int qtile = gridDim.x - 1 - blockIdx.x;
    const int h = blockIdx.y, b = blockIdx.z;
    const int kvh = h >> 2;

    const size_t qbase = ((size_t)(b * NH + h) * SEQ + qtile * AQ) * HD;
    const size_t kbase = ((size_t)(b * NKV + kvh) * SEQ) * HD;

    for (int i = tid; i < AQ * 16; i += 256) {
        int row = i >> 4, c = i & 15;
        uint32_t d = sb + row * (ASTR * 2) + c * 16;
        const size_t src = qbase + (size_t)row * HD + c * 8;
        cp16(d, Qhi + src);
        cp16(d + Q_BYTES, Qlo + src);
    }
    {
        uint32_t dst0 = sb + 2 * Q_BYTES;
        for (int i = tid; i < AKT * 16; i += 256) {
            int row = i >> 4, c = i & 15;
            uint32_t d = dst0 + row * (ASTR * 2) + c * 16;
            const size_t src = kbase + (size_t)row * HD + c * 8;
            cp16(d,                Khi + src);
            cp16(d + KV_BYTES,     Klo + src);
            cp16(d + 2 * KV_BYTES, Vhi + src);
            cp16(d + 3 * KV_BYTES, Vlo + src);
        }
    }
    CP_COMMIT();

    float oacc[16][4];
#pragma unroll
    for (int n = 0; n < 16; n++)
#pragma unroll
        for (int q = 0; q < 4; q++) oacc[n][q] = 0.f;
    float m0 = -1e30f, m1 = -1e30f, l0 = 0.f, l1 = 0.f;

    const uint32_t aRow = wid * 16 + (lane & 15);
    const uint32_t aColP = (lane >> 4) * 8;
    const uint32_t qAddr = sb + (aRow * ASTR + aColP) * 2;
    const uint32_t bRowP = (lane & 7) + ((lane >> 4) & 1) * 8;
    const uint32_t bColP = ((lane >> 3) & 1) * 8;
    const uint32_t vRowP = (lane & 7) + ((lane >> 3) & 1) * 8;
    const uint32_t vColP = (lane >> 4) * 8;

    const int nkt = 2 * qtile + 2;
    const int row0g = qtile * AQ + wid * 16 + (lane >> 2);

    for (int kt = 0; kt < nkt; ++kt) {
        const int s = kt & 1;
        CP_WAIT0();
        __syncthreads();
        if (kt + 1 < nkt) {
            uint32_t dst0 = sb + 2 * Q_BYTES + (s ^ 1) * KVBUF;
            const size_t kvoff = kbase + (size_t)(kt + 1) * AKT * HD;
            for (int i = tid; i < AKT * 16; i += 256) {
                int row = i >> 4, c = i & 15;
                uint32_t d = dst0 + row * (ASTR * 2) + c * 16;
                const size_t src = kvoff + (size_t)row * HD + c * 8;
                cp16(d,                Khi + src);
                cp16(d + KV_BYTES,     Klo + src);
                cp16(d + 2 * KV_BYTES, Vhi + src);
                cp16(d + 3 * KV_BYTES, Vlo + src);
            }
            CP_COMMIT();
        }

        const uint32_t kvb = sb + 2 * Q_BYTES + s * KVBUF;

        float sacc[8][4];
#pragma unroll
        for (int n = 0; n < 8; n++)
#pragma unroll
            for (int q = 0; q < 4; q++) sacc[n][q] = 0.f;

#pragma unroll
        for (int ks = 0; ks < 8; ++ks) {
            uint32_t aq[4], aql[4];
            uint32_t qa = qAddr + ks * 32;
            ldsm_x4(aq, qa);
            ldsm_x4(aql, qa + Q_BYTES);
            uint32_t bh[4][4], bl[4][4];
#pragma unroll
            for (int p = 0; p < 4; ++p) {
                uint32_t ba = kvb + ((p * 16 + bRowP) * ASTR + ks * 16 + bColP) * 2;
                ldsm_x4(bh[p], ba);
                ldsm_x4(bl[p], ba + KV_BYTES);
            }
#pragma unroll
            for (int nt = 0; nt < 8; ++nt) {
                uint32_t h0 = bh[nt >> 1][(nt & 1) * 2];
                uint32_t h1 = bh[nt >> 1][(nt & 1) * 2 + 1];
                uint32_t q0 = bl[nt >> 1][(nt & 1) * 2];
                uint32_t q1 = bl[nt >> 1][(nt & 1) * 2 + 1];
                mma_bf16(sacc[nt], aq, h0, h1);
                mma_bf16(sacc[nt], aq, q0, q1);
                mma_bf16(sacc[nt], aql, h0, h1);
            }
        }

        if (kt * AKT + AKT - 1 > qtile * AQ + wid * 16) {
            const int colb = kt * AKT + (lane & 3) * 2;
#pragma unroll
            for (int nt = 0; nt < 8; ++nt) {
                int c0 = colb + nt * 8;
                if (c0 > row0g)         sacc[nt][0] = -1e30f;
                if (c0 + 1 > row0g)     sacc[nt][1] = -1e30f;
                if (c0 > row0g + 8)     sacc[nt][2] = -1e30f;
                if (c0 + 1 > row0g + 8) sacc[nt][3] = -1e30f;
            }
        }

        float mx0 = -1e30f, mx1 = -1e30f;
#pragma unroll
        for (int nt = 0; nt < 8; ++nt) {
            mx0 = fmaxf(mx0, fmaxf(sacc[nt][0], sacc[nt][1]));
            mx1 = fmaxf(mx1, fmaxf(sacc[nt][2], sacc[nt][3]));
        }
        mx0 = fmaxf(mx0, __shfl_xor_sync(0xffffffffu, mx0, 1));
        mx0 = fmaxf(mx0, __shfl_xor_sync(0xffffffffu, mx0, 2));
        mx1 = fmaxf(mx1, __shfl_xor_sync(0xffffffffu, mx1, 1));
        mx1 = fmaxf(mx1, __shfl_xor_sync(0xffffffffu, mx1, 2));
        float nm0 = fmaxf(m0, mx0), nm1 = fmaxf(m1, mx1);
        float r0 = 0.f, r1 = 0.f;
#pragma unroll
        for (int nt = 0; nt < 8; ++nt) {
            sacc[nt][0] = __expf(sacc[nt][0] - nm0);
            sacc[nt][1] = __expf(sacc[nt][1] - nm0);
            sacc[nt][2] = __expf(sacc[nt][2] - nm1);
            sacc[nt][3] = __expf(sacc[nt][3] - nm1);
            r0 += sacc[nt][0] + sacc[nt][1];
            r1 += sacc[nt][2] + sacc[nt][3];
        }
        r0 += __shfl_xor_sync(0xffffffffu, r0, 1);
        r0 += __shfl_xor_sync(0xffffffffu, r0, 2);
        r1 += __shfl_xor_sync(0xffffffffu, r1, 1);
        r1 += __shfl_xor_sync(0xffffffffu, r1, 2);
        float a0 = __expf(m0 - nm0), a1 = __expf(m1 - nm1);
        l0 = l0 * a0 + r0;
        l1 = l1 * a1 + r1;
        m0 = nm0; m1 = nm1;
#pragma unroll
        for (int n = 0; n < 16; ++n) {
            oacc[n][0] *= a0; oacc[n][1] *= a0;
            oacc[n][2] *= a1; oacc[n][3] *= a1;
        }

        uint32_t ph[8][2], pl[8][2];
#pragma unroll
        for (int nt = 0; nt < 8; ++nt) {
            uint32_t u0 = __float_as_uint(sacc[nt][0]);
            uint32_t u1 = __float_as_uint(sacc[nt][1]);
            uint32_t u2 = __float_as_uint(sacc[nt][2]);
            uint32_t u3 = __float_as_uint(sacc[nt][3]);
            ph[nt][0] = __byte_perm(u0, u1, 0x7632);
            ph[nt][1] = __byte_perm(u2, u3, 0x7632);
            float e0 = sacc[nt][0] - __uint_as_float(u0 & 0xFFFF0000u);
            float e1 = sacc[nt][1] - __uint_as_float(u1 & 0xFFFF0000u);
            float e2 = sacc[nt][2] - __uint_as_float(u2 & 0xFFFF0000u);
            float e3 = sacc[nt][3] - __uint_as_float(u3 & 0xFFFF0000u);
            __nv_bfloat162 p01 = __floats2bfloat162_rn(e0, e1);
            __nv_bfloat162 p23 = __floats2bfloat162_rn(e2, e3);
            pl[nt][0] = *reinterpret_cast<uint32_t*>(&p01);
            pl[nt][1] = *reinterpret_cast<uint32_t*>(&p23);
        }

        const uint32_t vbase = kvb + 2 * KV_BYTES;
#pragma unroll
        for (int kk = 0; kk < 4; ++kk) {
            uint32_t pa[4]  = { ph[2 * kk][0], ph[2 * kk][1], ph[2 * kk + 1][0], ph[2 * kk + 1][1] };
            uint32_t pal[4] = { pl[2 * kk][0], pl[2 * kk][1], pl[2 * kk + 1][0], pl[2 * kk + 1][1] };
#pragma unroll
            for (int nt = 0; nt < 8; ++nt) {
                uint32_t va = vbase + ((kk * 16 + vRowP) * ASTR + nt * 16 + vColP) * 2;
                uint32_t vh[4], vl[4];
                ldsm_x4_t(vh, va);
                ldsm_x4_t(vl, va + KV_BYTES);
                mma_bf16(oacc[2 * nt],     pa,  vh[0], vh[1]);
                mma_bf16(oacc[2 * nt],     pa,  vl[0], vl[1]);
                mma_bf16(oacc[2 * nt],     pal, vh[0], vh[1]);
                mma_bf16(oacc[2 * nt + 1], pa,  vh[2], vh[3]);
                mma_bf16(oacc[2 * nt + 1], pa,  vl[2], vl[3]);
                mma_bf16(oacc[2 * nt + 1], pal, vh[2], vh[3]);
            }
        }
    }

    // ---- epilogue: normalize + split to bf16 hi/lo ----
    float inv0 = 1.0f / l0, inv1 = 1.0f / l1;
    const int trow = b * SEQ + row0g;
    const int cc = (lane & 3) * 2;
#pragma unroll
    for (int nt = 0; nt < 16; ++nt) {
        int col = h * HD + nt * 8 + cc;
        float o0 = oacc[nt][0] * inv0, o1 = oacc[nt][1] * inv0;
        float o2 = oacc[nt][2] * inv1, o3 = oacc[nt][3] * inv1;
        uint32_t u0 = __float_as_uint(o0), u1 = __float_as_uint(o1);
        uint32_t u2 = __float_as_uint(o2), u3 = __float_as_uint(o3);
        uint32_t hi01 = __byte_perm(u0, u1, 0x7632);
        uint32_t hi23 = __byte_perm(u2, u3, 0x7632);
        __nv_bfloat162 lo01 = __floats2bfloat162_rn(
            o0 - __uint_as_float(u0 & 0xFFFF0000u), o1 - __uint_as_float(u1 & 0xFFFF0000u));
        __nv_bfloat162 lo23 = __floats2bfloat162_rn(
            o2 - __uint_as_float(u2 & 0xFFFF0000u), o3 - __uint_as_float(u3 & 0xFFFF0000u));
        *reinterpret_cast<uint32_t*>(&Ohi[(size_t)trow * HID + col]) = hi01;
        *reinterpret_cast<uint32_t*>(&Olo[(size_t)trow * HID + col]) =
            *reinterpret_cast<uint32_t*>(&lo01);
        *reinterpret_cast<uint32_t*>(&Ohi[(size_t)(trow + 8) * HID + col]) = hi23;
        *reinterpret_cast<uint32_t*>(&Olo[(size_t)(trow + 8) * HID + col]) =
            *reinterpret_cast<uint32_t*>(&lo23);
    }
}

// ---------------------------------------------------------------------------
extern "C" void kernel_launch(void* const* d_in, const int* in_sizes, int n_in,
                              void* d_out, int out_size) {
    const float* hs    = (const float*)d_in[0];
    const float* w_qkv = (const float*)d_in[1];
    const float* w_o   = (const float*)d_in[2];
    float* out = (float*)d_out;

    float* qkv = nullptr;
    __nv_bfloat16 *hshi, *hslo, *wqhi, *wqlo, *wohi, *wolo, *atthi, *attlo;
    __nv_bfloat16 *qhi, *qlo, *khi, *klo, *vhi, *vlo;
    cudaGetSymbolAddress((void**)&qkv, g_qkv);
    cudaGetSymbolAddress((void**)&hshi, g_hshi);
    cudaGetSymbolAddress((void**)&hslo, g_hslo);
    cudaGetSymbolAddress((void**)&wqhi, g_wqhi);
    cudaGetSymbolAddress((void**)&wqlo, g_wqlo);
    cudaGetSymbolAddress((void**)&wohi, g_wohi);
    cudaGetSymbolAddress((void**)&wolo, g_wolo);
    cudaGetSymbolAddress((void**)&atthi, g_atthi);
    cudaGetSymbolAddress((void**)&attlo, g_attlo);
    cudaGetSymbolAddress((void**)&qhi, g_qhi);
    cudaGetSymbolAddress((void**)&qlo, g_qlo);
    cudaGetSymbolAddress((void**)&khi, g_khi);
    cudaGetSymbolAddress((void**)&klo, g_klo);
    cudaGetSymbolAddress((void**)&vhi, g_vhi);
    cudaGetSymbolAddress((void**)&vlo, g_vlo);

    cudaFuncSetAttribute(gemm_w16b, cudaFuncAttributeMaxDynamicSharedMemorySize, GEMM_SMEM);
    cudaFuncSetAttribute(attn_mma, cudaFuncAttributeMaxDynamicSharedMemorySize, ATT_SMEM);

    // 0) pre-split inputs and weights to bf16 hi/lo
    split2<<<(TT * HID / 8 + 255) / 256, 256>>>(hs, hshi, hslo, TT * HID / 8);
    split2<<<(QKVD * HID / 8 + 255) / 256, 256>>>(w_qkv, wqhi, wqlo, QKVD * HID / 8);
    split2<<<(HID * HID / 8 + 255) / 256, 256>>>(w_o, wohi, wolo, HID * HID / 8);

    // 1) QKV projection
    {
        dim3 grid(QKVD / GBN, TT / GBM);
        gemm_w16b<<<grid, GTHREADS, GEMM_SMEM>>>(hshi, hslo, wqhi, wqlo, qkv, TT, QKVD, HID);
    }
    // 2) fused RoPE + split to bf16 hi/lo (head-major)
    {
        int total = TT * (NH + 2 * NKV) * 64;
        rope_split<<<total / 256, 256>>>(qkv, qhi, qlo, khi, klo, vhi, vlo);
    }
    // 3) tensor-core causal GQA attention -> split bf16 output
    {
        dim3 grid(SEQ / AQ, NH, NB);
        attn_mma<<<grid, 256, ATT_SMEM>>>(qhi, qlo, khi, klo, vhi, vlo, atthi, attlo);
    }
    // 4) output projection
    {
        dim3 grid(HID / GBN, TT / GBM);
        gemm_w16b<<<grid, GTHREADS, GEMM_SMEM>>>(atthi, attlo, wohi, wolo, out, TT, HID, HID);
    }
}

// round 12
// speedup vs baseline: 1.1390x; 1.0484x over previous
#include <cuda_runtime.h>
#include <cuda_bf16.h>
#include <math.h>
#include <stdint.h>

#define TT    4096      // BATCH * SEQ tokens
#define HID   4096
#define NH    32
#define NKV   8
#define HD    128
#define QKVD  6144      // (32 + 16) * 128
#define SEQ   1024
#define NB    4

// Scratch (static device globals; no runtime allocation)
__device__ float g_qkv[(size_t)TT * QKVD];   // 96 MB
// pre-split bf16 operand buffers
__device__ __nv_bfloat16 g_hshi[(size_t)TT * HID];
__device__ __nv_bfloat16 g_hslo[(size_t)TT * HID];
__device__ __nv_bfloat16 g_wqhi[(size_t)QKVD * HID];
__device__ __nv_bfloat16 g_wqlo[(size_t)QKVD * HID];
__device__ __nv_bfloat16 g_wohi[(size_t)HID * HID];
__device__ __nv_bfloat16 g_wolo[(size_t)HID * HID];
__device__ __nv_bfloat16 g_atthi[(size_t)TT * HID];
__device__ __nv_bfloat16 g_attlo[(size_t)TT * HID];
// split bf16 q/k/v (head-major)
__device__ __nv_bfloat16 g_qhi[(size_t)NB * NH * SEQ * HD];
__device__ __nv_bfloat16 g_qlo[(size_t)NB * NH * SEQ * HD];
__device__ __nv_bfloat16 g_khi[(size_t)NB * NKV * SEQ * HD];
__device__ __nv_bfloat16 g_klo[(size_t)NB * NKV * SEQ * HD];
__device__ __nv_bfloat16 g_vhi[(size_t)NB * NKV * SEQ * HD];
__device__ __nv_bfloat16 g_vlo[(size_t)NB * NKV * SEQ * HD];

// ===========================================================================
// helpers
// ===========================================================================
__device__ __forceinline__ uint32_t smem_u32(const void* p) {
    uint32_t a;
    asm("{ .reg .u64 t; cvta.to.shared.u64 t, %1; cvt.u32.u64 %0, t; }"
        : "=r"(a) : "l"(p));
    return a;
}
__device__ __forceinline__ void ldsm_x4(uint32_t* r, uint32_t addr) {
    asm volatile("ldmatrix.sync.aligned.m8n8.x4.shared.b16 {%0,%1,%2,%3}, [%4];"
                 : "=r"(r[0]), "=r"(r[1]), "=r"(r[2]), "=r"(r[3]) : "r"(addr));
}
__device__ __forceinline__ void ldsm_x4_t(uint32_t* r, uint32_t addr) {
    asm volatile("ldmatrix.sync.aligned.m8n8.x4.trans.shared.b16 {%0,%1,%2,%3}, [%4];"
                 : "=r"(r[0]), "=r"(r[1]), "=r"(r[2]), "=r"(r[3]) : "r"(addr));
}
__device__ __forceinline__ void mma_bf16(float* c, const uint32_t* a,
                                         uint32_t b0, uint32_t b1) {
    asm volatile(
        "mma.sync.aligned.m16n8k16.row.col.f32.bf16.bf16.f32 "
        "{%0,%1,%2,%3}, {%4,%5,%6,%7}, {%8,%9}, {%0,%1,%2,%3};"
        : "+f"(c[0]), "+f"(c[1]), "+f"(c[2]), "+f"(c[3])
        : "r"(a[0]), "r"(a[1]), "r"(a[2]), "r"(a[3]), "r"(b0), "r"(b1));
}
__device__ __forceinline__ void cp16(uint32_t dst, const void* src) {
    asm volatile("cp.async.cg.shared.global [%0], [%1], 16;" :: "r"(dst), "l"(src));
}
#define CP_COMMIT() asm volatile("cp.async.commit_group;" ::: "memory")
#define CP_WAIT0()  asm volatile("cp.async.wait_group 0;" ::: "memory")
#define CP_WAIT1()  asm volatile("cp.async.wait_group 1;" ::: "memory")

// split 4 fp32 -> packed hi bf16x2 pair + lo bf16x2 pair
__device__ __forceinline__ void split4(float4 f, uint32_t* hi, uint32_t* lo) {
    uint32_t x0 = __float_as_uint(f.x), x1 = __float_as_uint(f.y);
    uint32_t x2 = __float_as_uint(f.z), x3 = __float_as_uint(f.w);
    hi[0] = __byte_perm(x0, x1, 0x7632);
    hi[1] = __byte_perm(x2, x3, 0x7632);
    float l0 = f.x - __uint_as_float(x0 & 0xFFFF0000u);
    float l1 = f.y - __uint_as_float(x1 & 0xFFFF0000u);
    float l2 = f.z - __uint_as_float(x2 & 0xFFFF0000u);
    float l3 = f.w - __uint_as_float(x3 & 0xFFFF0000u);
    __nv_bfloat162 b0 = __floats2bfloat162_rn(l0, l1);
    __nv_bfloat162 b1 = __floats2bfloat162_rn(l2, l3);
    lo[0] = *reinterpret_cast<uint32_t*>(&b0);
    lo[1] = *reinterpret_cast<uint32_t*>(&b1);
}

// ===========================================================================
// split2: fp32 buffer -> bf16 hi/lo buffers.  8 elements per thread.
// ===========================================================================
__global__ __launch_bounds__(256) void split2(const float* __restrict__ src,
                                              __nv_bfloat16* __restrict__ hi,
                                              __nv_bfloat16* __restrict__ lo,
                                              int n8) {
    int i = blockIdx.x * 256 + threadIdx.x;
    if (i >= n8) return;
    const float4* s = reinterpret_cast<const float4*>(src) + (size_t)i * 2;
    float4 f0 = s[0], f1 = s[1];
    uint32_t h0[2], l0[2], h1[2], l1[2];
    split4(f0, h0, l0);
    split4(f1, h1, l1);
    *reinterpret_cast<uint4*>(hi + (size_t)i * 8) = make_uint4(h0[0], h0[1], h1[0], h1[1]);
    *reinterpret_cast<uint4*>(lo + (size_t)i * 8) = make_uint4(l0[0], l0[1], l1[0], l1[1]);
}

// ===========================================================================
// gemm_ps3 (NT): C = (Ahi+Alo) @ (Bhi+Blo)^T, bf16 in, fp32 out.
// R7 config (best measured) with PRODUCT-MAJOR MMA ordering: each of the 3
// split-products sweeps all 16 output tiles before the next, so adjacent
// MMAs never share an accumulator (no dependent C-chains).
// BK=64, 3-stage cp.async pipeline, register-double-buffered fragments.
// 256 threads, 8 warps (4Mx2N), warp tile 32x64, occ 1.
// ===========================================================================
#define GBM 128
#define GBN 128
#define GKB 64
#define GSTR 72                        // element stride (144B row)
#define GTILEB (128 * GSTR * 2)        // 18432 B per tensor tile
#define GSTAGEB (4 * GTILEB)           // 73728 B per stage
#define GEMM_SMEM (3 * GSTAGEB)        // 221184 B

__global__ __launch_bounds__(256, 1) void gemm_ps3(
        const __nv_bfloat16* __restrict__ Ahi, const __nv_bfloat16* __restrict__ Alo,
        const __nv_bfloat16* __restrict__ Bhi, const __nv_bfloat16* __restrict__ Blo,
        float* __restrict__ C, int M, int N, int K) {
    extern __shared__ char sm8[];
    const uint32_t sb = smem_u32(sm8);
    const int tid = threadIdx.x;
    const int wid = tid >> 5;
    const int lane = tid & 31;
    const int wm = wid & 3;
    const int wn = wid >> 2;
    const int bm = blockIdx.y * GBM;
    const int bn = blockIdx.x * GBN;

    float acc[2][8][4];
#pragma unroll
    for (int i = 0; i < 2; i++)
#pragma unroll
        for (int j = 0; j < 8; j++)
#pragma unroll
            for (int q = 0; q < 4; q++) acc[i][j][q] = 0.f;

    // ldsm fragment base offsets (bytes)
    const uint32_t aOffB = ((wm * 32 + (lane & 15)) * GSTR + (lane >> 4) * 8) * 2;
    const uint32_t bOffB = ((wn * 64 + (lane & 7) + ((lane >> 4) & 1) * 8) * GSTR
                           + ((lane >> 3) & 1) * 8) * 2;

    // cp.async mapping: per tensor 1024 16B-chunks (row = i>>3, c = i&7)
    const int r0 = tid >> 3;                 // rows r0, r0+32, r0+64, r0+96
    const int cc0 = tid & 7;

    auto load_stage = [&](uint32_t base, int k0) {
#pragma unroll
        for (int u = 0; u < 4; ++u) {
            int row = r0 + u * 32;
            uint32_t d = base + row * (GSTR * 2) + cc0 * 16;
            size_t ao = (size_t)(bm + row) * K + k0 + cc0 * 8;
            size_t bo = (size_t)(bn + row) * K + k0 + cc0 * 8;
            cp16(d, Ahi + ao);
            cp16(d + GTILEB, Alo + ao);
            cp16(d + 2 * GTILEB, Bhi + bo);
            cp16(d + 3 * GTILEB, Blo + bo);
        }
    };

    const int NC = K / GKB;      // 64

    // prologue: stages 0, 1
    load_stage(sb, 0);
    CP_COMMIT();
    load_stage(sb + GSTAGEB, GKB);
    CP_COMMIT();

    int scur = 0, snext = 2;     // stage holding kc ; stage to fill with kc+2

    for (int kc = 0; kc < NC; ++kc) {
        if (kc == NC - 1) { CP_WAIT0(); } else { CP_WAIT1(); }
        __syncthreads();
        if (kc + 2 < NC) {
            load_stage(sb + snext * GSTAGEB, (kc + 2) * GKB);
            CP_COMMIT();
        }
        const uint32_t base = sb + scur * GSTAGEB;
        scur = (scur == 2) ? 0 : scur + 1;
        snext = (snext == 2) ? 0 : snext + 1;

        // fragment double-buffer over the 4 k16-steps
        uint32_t ah[2][2][4], al[2][2][4], bh[2][4][4], bl[2][4][4];

#pragma unroll
        for (int mt = 0; mt < 2; ++mt) {
            uint32_t aa = base + aOffB + mt * (16 * GSTR * 2);
            ldsm_x4(ah[0][mt], aa);
            ldsm_x4(al[0][mt], aa + GTILEB);
        }
#pragma unroll
        for (int p = 0; p < 4; ++p) {
            uint32_t ba = base + 2 * GTILEB + bOffB + p * (16 * GSTR * 2);
            ldsm_x4(bh[0][p], ba);
            ldsm_x4(bl[0][p], ba + GTILEB);
        }

#pragma unroll
        for (int ks = 0; ks < 4; ++ks) {
            const int cur = ks & 1, nxt = cur ^ 1;
            if (ks < 3) {
                const uint32_t ko = (ks + 1) * 32;
#pragma unroll
                for (int mt = 0; mt < 2; ++mt) {
                    uint32_t aa = base + aOffB + mt * (16 * GSTR * 2) + ko;
                    ldsm_x4(ah[nxt][mt], aa);
                    ldsm_x4(al[nxt][mt], aa + GTILEB);
                }
#pragma unroll
                for (int p = 0; p < 4; ++p) {
                    uint32_t ba = base + 2 * GTILEB + bOffB + p * (16 * GSTR * 2) + ko;
                    ldsm_x4(bh[nxt][p], ba);
                    ldsm_x4(bl[nxt][p], ba + GTILEB);
                }
            }
            // --- product-major: 3 passes, each touching all 16 acc tiles ---
#pragma unroll
            for (int prod = 0; prod < 3; ++prod) {
#pragma unroll
                for (int p = 0; p < 4; ++p)
#pragma unroll
                    for (int n2 = 0; n2 < 2; ++n2) {
                        const int nt = p * 2 + n2;
                        uint32_t b0, b1;
                        if (prod == 1) {          // hi * lo
                            b0 = bl[cur][p][n2 * 2]; b1 = bl[cur][p][n2 * 2 + 1];
                        } else {                  // hi * hi  /  lo * hi
                            b0 = bh[cur][p][n2 * 2]; b1 = bh[cur][p][n2 * 2 + 1];
                        }
#pragma unroll
                        for (int mt = 0; mt < 2; ++mt) {
                            const uint32_t* af = (prod == 2) ? al[cur][mt] : ah[cur][mt];
                            mma_bf16(acc[mt][nt], af, b0, b1);
                        }
                    }
            }
        }
    }

    const int g = lane >> 2;
    const int cc = (lane & 3) * 2;
#pragma unroll
    for (int mt = 0; mt < 2; ++mt) {
        int rowc = bm + wm * 32 + mt * 16 + g;
#pragma unroll
        for (int nt = 0; nt < 8; ++nt) {
            int col = bn + wn * 64 + nt * 8 + cc;
            *reinterpret_cast<float2*>(&C[(size_t)rowc * N + col]) =
                make_float2(acc[mt][nt][0], acc[mt][nt][1]);
            *reinterpret_cast<float2*>(&C[(size_t)(rowc + 8) * N + col]) =
                make_float2(acc[mt][nt][2], acc[mt][nt][3]);
        }
    }
}

// ===========================================================================
// fused RoPE + head-major split to bf16 hi/lo.  Q gets 1/sqrt(128) folded in.
// ===========================================================================
__global__ __launch_bounds__(256) void rope_split(const float* __restrict__ qkv,
        __nv_bfloat16* __restrict__ qhi, __nv_bfloat16* __restrict__ qlo,
        __nv_bfloat16* __restrict__ khi, __nv_bfloat16* __restrict__ klo,
        __nv_bfloat16* __restrict__ vhi, __nv_bfloat16* __restrict__ vlo) {
    int x = blockIdx.x * 256 + threadIdx.x;
    int i = x & 63;
    int r = x >> 6;
    int hh = r % (NH + 2 * NKV);
    int t = r / (NH + 2 * NKV);
    int b = t >> 10;
    int s = t & (SEQ - 1);

    const float* base = qkv + (size_t)t * QKVD + hh * HD;
    float x1 = base[i];
    float x2 = base[i + 64];
    float y1, y2;
    if (hh < NH + NKV) {
        // invf = 10000^(-2i/128) = exp2(-(2i/128)*log2(10000))
        const float L2T = 13.287712379549449f;   // log2(10000)
        float invf = exp2f(-(float)(2 * i) * (1.0f / (float)HD) * L2T);
        float ang = (float)s * invf;
        float sn, cs;
        sincosf(ang, &sn, &cs);
        y1 = x1 * cs - x2 * sn;
        y2 = x2 * cs + x1 * sn;
    } else { y1 = x1; y2 = x2; }

    __nv_bfloat16 *dh, *dl;
    size_t off;
    if (hh < NH) {
        const float sc = 0.08838834764831845f;
        y1 *= sc; y2 *= sc;
        off = ((size_t)(b * NH + hh) * SEQ + s) * HD;
        dh = qhi; dl = qlo;
    } else if (hh < NH + NKV) {
        off = ((size_t)(b * NKV + (hh - NH)) * SEQ + s) * HD;
        dh = khi; dl = klo;
    } else {
        off = ((size_t)(b * NKV + (hh - NH - NKV)) * SEQ + s) * HD;
        dh = vhi; dl = vlo;
    }
    uint32_t u1 = __float_as_uint(y1), u2 = __float_as_uint(y2);
    float h1 = __uint_as_float(u1 & 0xFFFF0000u);
    float h2 = __uint_as_float(u2 & 0xFFFF0000u);
    dh[off + i]      = __float2bfloat16(h1);
    dh[off + i + 64] = __float2bfloat16(h2);
    dl[off + i]      = __float2bfloat16(y1 - h1);
    dl[off + i + 64] = __float2bfloat16(y2 - h2);
}

// ===========================================================================
// Tensor-core causal GQA flash attention (bf16x3 split).
// Epilogue writes split bf16 hi/lo directly (feeds O-proj GEMM).
// ===========================================================================
#define AQ   128
#define AKT  64
#define ASTR 136
#define Q_BYTES   (AQ * ASTR * 2)
#define KV_BYTES  (AKT * ASTR * 2)
#define KVBUF     (4 * KV_BYTES)
#define ATT_SMEM  (2 * Q_BYTES + 2 * KVBUF)

__global__ __launch_bounds__(256) void attn_mma(
        const __nv_bfloat16* __restrict__ Qhi, const __nv_bfloat16* __restrict__ Qlo,
        const __nv_bfloat16* __restrict__ Khi, const __nv_bfloat16* __restrict__ Klo,
        const __nv_bfloat16* __restrict__ Vhi, const __nv_bfloat16* __restrict__ Vlo,
        __nv_bfloat16* __restrict__ Ohi, __nv_bfloat16* __restrict__ Olo) {
    extern __shared__ char sm8[];
    const uint32_t sb = smem_u32(sm8);
    const int tid = threadIdx.x, wid = tid >> 5, lane = tid & 31;
    const int qtile = gridDim.x - 1 - blockIdx.x;
    const int h = blockIdx.y, b = blockIdx.z;
    const int kvh = h >> 2;

    const size_t qbase = ((size_t)(b * NH + h) * SEQ + qtile * AQ) * HD;
    const size_t kbase = ((size_t)(b * NKV + kvh) * SEQ) * HD;

    for (int i = tid; i < AQ * 16; i += 256) {
        int row = i >> 4, c = i & 15;
        uint32_t d = sb + row * (ASTR * 2) + c * 16;
        const size_t src = qbase + (size_t)row * HD + c * 8;
        cp16(d, Qhi + src);
        cp16(d + Q_BYTES, Qlo + src);
    }
    {
        uint32_t dst0 = sb + 2 * Q_BYTES;
        for (int i = tid; i < AKT * 16; i += 256) {
            int row = i >> 4, c = i & 15;
            uint32_t d = dst0 + row * (ASTR * 2) + c * 16;
            const size_t src = kbase + (size_t)row * HD + c * 8;
            cp16(d,                Khi + src);
            cp16(d + KV_BYTES,     Klo + src);
            cp16(d + 2 * KV_BYTES, Vhi + src);
            cp16(d + 3 * KV_BYTES, Vlo + src);
        }
    }
    CP_COMMIT();

    float oacc[16][4];
#pragma unroll
    for (int n = 0; n < 16; n++)
#pragma unroll
        for (int q = 0; q < 4; q++) oacc[n][q] = 0.f;
    float m0 = -1e30f, m1 = -1e30f, l0 = 0.f, l1 = 0.f;

    const uint32_t aRow = wid * 16 + (lane & 15);
    const uint32_t aColP = (lane >> 4) * 8;
    const uint32_t qAddr = sb + (aRow * ASTR + aColP) * 2;
    const uint32_t bRowP = (lane & 7) + ((lane >> 4) & 1) * 8;
    const uint32_t bColP = ((lane >> 3) & 1) * 8;
    const uint32_t vRowP = (lane & 7) + ((lane >> 3) & 1) * 8;
    const uint32_t vColP = (lane >> 4) * 8;

    const int nkt = 2 * qtile + 2;
    const int row0g = qtile * AQ + wid * 16 + (lane >> 2);

    for (int kt = 0; kt < nkt; ++kt) {
        const int s = kt & 1;
        CP_WAIT0();
        __syncthreads();
        if (kt + 1 < nkt) {
            uint32_t dst0 = sb + 2 * Q_BYTES + (s ^ 1) * KVBUF;
            const size_t kvoff = kbase + (size_t)(kt + 1) * AKT * HD;
            for (int i = tid; i < AKT * 16; i += 256) {
                int row = i >> 4, c = i & 15;
                uint32_t d = dst0 + row * (ASTR * 2) + c * 16;
                const size_t src = kvoff + (size_t)row * HD + c * 8;
                cp16(d,                Khi + src);
                cp16(d + KV_BYTES,     Klo + src);
                cp16(d + 2 * KV_BYTES, Vhi + src);
                cp16(d + 3 * KV_BYTES, Vlo + src);
            }
            CP_COMMIT();
        }

        const uint32_t kvb = sb + 2 * Q_BYTES + s * KVBUF;

        float sacc[8][4];
#pragma unroll
        for (int n = 0; n < 8; n++)
#pragma unroll
            for (int q = 0; q < 4; q++) sacc[n][q] = 0.f;

#pragma unroll
        for (int ks = 0; ks < 8; ++ks) {
            uint32_t aq[4], aql[4];
            uint32_t qa = qAddr + ks * 32;
            ldsm_x4(aq, qa);
            ldsm_x4(aql, qa + Q_BYTES);
            uint32_t bh[4][4], bl[4][4];
#pragma unroll
            for (int p = 0; p < 4; ++p) {
                uint32_t ba = kvb + ((p * 16 + bRowP) * ASTR + ks * 16 + bColP) * 2;
                ldsm_x4(bh[p], ba);
                ldsm_x4(bl[p], ba + KV_BYTES);
            }
#pragma unroll
            for (int nt = 0; nt < 8; ++nt) {
                uint32_t h0 = bh[nt >> 1][(nt & 1) * 2];
                uint32_t h1 = bh[nt >> 1][(nt & 1) * 2 + 1];
                uint32_t q0 = bl[nt >> 1][(nt & 1) * 2];
                uint32_t q1 = bl[nt >> 1][(nt & 1) * 2 + 1];
                mma_bf16(sacc[nt], aq, h0, h1);
                mma_bf16(sacc[nt], aq, q0, q1);
                mma_bf16(sacc[nt], aql, h0, h1);
            }
        }

        if (kt * AKT + AKT - 1 > qtile * AQ + wid * 16) {
            const int colb = kt * AKT + (lane & 3) * 2;
#pragma unroll
            for (int nt = 0; nt < 8; ++nt) {
                int c0 = colb + nt * 8;
                if (c0 > row0g)         sacc[nt][0] = -1e30f;
                if (c0 + 1 > row0g)     sacc[nt][1] = -1e30f;
                if (c0 > row0g + 8)     sacc[nt][2] = -1e30f;
                if (c0 + 1 > row0g + 8) sacc[nt][3] = -1e30f;
            }
        }

        float mx0 = -1e30f, mx1 = -1e30f;
#pragma unroll
        for (int nt = 0; nt < 8; ++nt) {
            mx0 = fmaxf(mx0, fmaxf(sacc[nt][0], sacc[nt][1]));
            mx1 = fmaxf(mx1, fmaxf(sacc[nt][2], sacc[nt][3]));
        }
        mx0 = fmaxf(mx0, __shfl_xor_sync(0xffffffffu, mx0, 1));
        mx0 = fmaxf(mx0, __shfl_xor_sync(0xffffffffu, mx0, 2));
        mx1 = fmaxf(mx1, __shfl_xor_sync(0xffffffffu, mx1, 1));
        mx1 = fmaxf(mx1, __shfl_xor_sync(0xffffffffu, mx1, 2));
        float nm0 = fmaxf(m0, mx0), nm1 = fmaxf(m1, mx1);
        float r0 = 0.f, r1 = 0.f;
#pragma unroll
        for (int nt = 0; nt < 8; ++nt) {
            sacc[nt][0] = __expf(sacc[nt][0] - nm0);
            sacc[nt][1] = __expf(sacc[nt][1] - nm0);
            sacc[nt][2] = __expf(sacc[nt][2] - nm1);
            sacc[nt][3] = __expf(sacc[nt][3] - nm1);
            r0 += sacc[nt][0] + sacc[nt][1];
            r1 += sacc[nt][2] + sacc[nt][3];
        }
        r0 += __shfl_xor_sync(0xffffffffu, r0, 1);
        r0 += __shfl_xor_sync(0xffffffffu, r0, 2);
        r1 += __shfl_xor_sync(0xffffffffu, r1, 1);
        r1 += __shfl_xor_sync(0xffffffffu, r1, 2);
        float a0 = __expf(m0 - nm0), a1 = __expf(m1 - nm1);
        l0 = l0 * a0 + r0;
        l1 = l1 * a1 + r1;
        m0 = nm0; m1 = nm1;
#pragma unroll
        for (int n = 0; n < 16; ++n) {
            oacc[n][0] *= a0; oacc[n][1] *= a0;
            oacc[n][2] *= a1; oacc[n][3] *= a1;
        }

        uint32_t ph[8][2], pl[8][2];
#pragma unroll
        for (int nt = 0; nt < 8; ++nt) {
            uint32_t u0 = __float_as_uint(sacc[nt][0]);
            uint32_t u1 = __float_as_uint(sacc[nt][1]);
            uint32_t u2 = __float_as_uint(sacc[nt][2]);
            uint32_t u3 = __float_as_uint(sacc[nt][3]);
            ph[nt][0] = __byte_perm(u0, u1, 0x7632);
            ph[nt][1] = __byte_perm(u2, u3, 0x7632);
            float e0 = sacc[nt][0] - __uint_as_float(u0 & 0xFFFF0000u);
            float e1 = sacc[nt][1] - __uint_as_float(u1 & 0xFFFF0000u);
            float e2 = sacc[nt][2] - __uint_as_float(u2 & 0xFFFF0000u);
            float e3 = sacc[nt][3] - __uint_as_float(u3 & 0xFFFF0000u);
            __nv_bfloat162 p01 = __floats2bfloat162_rn(e0, e1);
            __nv_bfloat162 p23 = __floats2bfloat162_rn(e2, e3);
            pl[nt][0] = *reinterpret_cast<uint32_t*>(&p01);
            pl[nt][1] = *reinterpret_cast<uint32_t*>(&p23);
        }

        const uint32_t vbase = kvb + 2 * KV_BYTES;
#pragma unroll
        for (int kk = 0; kk < 4; ++kk) {
            uint32_t pa[4]  = { ph[2 * kk][0], ph[2 * kk][1], ph[2 * kk + 1][0], ph[2 * kk + 1][1] };
            uint32_t pal[4] = { pl[2 * kk][0], pl[2 * kk][1], pl[2 * kk + 1][0], pl[2 * kk + 1][1] };
#pragma unroll
            for (int nt = 0; nt < 8; ++nt) {
                uint32_t va = vbase + ((kk * 16 + vRowP) * ASTR + nt * 16 + vColP) * 2;
                uint32_t vh[4], vl[4];
                ldsm_x4_t(vh, va);
                ldsm_x4_t(vl, va + KV_BYTES);
                mma_bf16(oacc[2 * nt],     pa,  vh[0], vh[1]);
                mma_bf16(oacc[2 * nt],     pa,  vl[0], vl[1]);
                mma_bf16(oacc[2 * nt],     pal, vh[0], vh[1]);
                mma_bf16(oacc[2 * nt + 1], pa,  vh[2], vh[3]);
                mma_bf16(oacc[2 * nt + 1], pa,  vl[2], vl[3]);
                mma_bf16(oacc[2 * nt + 1], pal, vh[2], vh[3]);
            }
        }
    }

    // ---- epilogue: normalize + split to bf16 hi/lo ----
    float inv0 = 1.0f / l0, inv1 = 1.0f / l1;
    const int trow = b * SEQ + row0g;
    const int cc = (lane & 3) * 2;
#pragma unroll
    for (int nt = 0; nt < 16; ++nt) {
        int col = h * HD + nt * 8 + cc;
        float o0 = oacc[nt][0] * inv0, o1 = oacc[nt][1] * inv0;
        float o2 = oacc[nt][2] * inv1, o3 = oacc[nt][3] * inv1;
        uint32_t u0 = __float_as_uint(o0), u1 = __float_as_uint(o1);
        uint32_t u2 = __float_as_uint(o2), u3 = __float_as_uint(o3);
        uint32_t hi01 = __byte_perm(u0, u1, 0x7632);
        uint32_t hi23 = __byte_perm(u2, u3, 0x7632);
        __nv_bfloat162 lo01 = __floats2bfloat162_rn(
            o0 - __uint_as_float(u0 & 0xFFFF0000u), o1 - __uint_as_float(u1 & 0xFFFF0000u));
        __nv_bfloat162 lo23 = __floats2bfloat162_rn(
            o2 - __uint_as_float(u2 & 0xFFFF0000u), o3 - __uint_as_float(u3 & 0xFFFF0000u));
        *reinterpret_cast<uint32_t*>(&Ohi[(size_t)trow * HID + col]) = hi01;
        *reinterpret_cast<uint32_t*>(&Olo[(size_t)trow * HID + col]) =
            *reinterpret_cast<uint32_t*>(&lo01);
        *reinterpret_cast<uint32_t*>(&Ohi[(size_t)(trow + 8) * HID + col]) = hi23;
        *reinterpret_cast<uint32_t*>(&Olo[(size_t)(trow + 8) * HID + col]) =
            *reinterpret_cast<uint32_t*>(&lo23);
    }
}

// ---------------------------------------------------------------------------
extern "C" void kernel_launch(void* const* d_in, const int* in_sizes, int n_in,
                              void* d_out, int out_size) {
    const float* hs    = (const float*)d_in[0];
    const float* w_qkv = (const float*)d_in[1];
    const float* w_o   = (const float*)d_in[2];
    float* out = (float*)d_out;

    float* qkv = nullptr;
    __nv_bfloat16 *hshi, *hslo, *wqhi, *wqlo, *wohi, *wolo, *atthi, *attlo;
    __nv_bfloat16 *qhi, *qlo, *khi, *klo, *vhi, *vlo;
    cudaGetSymbolAddress((void**)&qkv, g_qkv);
    cudaGetSymbolAddress((void**)&hshi, g_hshi);
    cudaGetSymbolAddress((void**)&hslo, g_hslo);
    cudaGetSymbolAddress((void**)&wqhi, g_wqhi);
    cudaGetSymbolAddress((void**)&wqlo, g_wqlo);
    cudaGetSymbolAddress((void**)&wohi, g_wohi);
    cudaGetSymbolAddress((void**)&wolo, g_wolo);
    cudaGetSymbolAddress((void**)&atthi, g_atthi);
    cudaGetSymbolAddress((void**)&attlo, g_attlo);
    cudaGetSymbolAddress((void**)&qhi, g_qhi);
    cudaGetSymbolAddress((void**)&qlo, g_qlo);
    cudaGetSymbolAddress((void**)&khi, g_khi);
    cudaGetSymbolAddress((void**)&klo, g_klo);
    cudaGetSymbolAddress((void**)&vhi, g_vhi);
    cudaGetSymbolAddress((void**)&vlo, g_vlo);

    cudaFuncSetAttribute(gemm_ps3, cudaFuncAttributeMaxDynamicSharedMemorySize, GEMM_SMEM);
    cudaFuncSetAttribute(attn_mma, cudaFuncAttributeMaxDynamicSharedMemorySize, ATT_SMEM);

    // 0) pre-split inputs and weights to bf16 hi/lo
    split2<<<(TT * HID / 8 + 255) / 256, 256>>>(hs, hshi, hslo, TT * HID / 8);
    split2<<<(QKVD * HID / 8 + 255) / 256, 256>>>(w_qkv, wqhi, wqlo, QKVD * HID / 8);
    split2<<<(HID * HID / 8 + 255) / 256, 256>>>(w_o, wohi, wolo, HID * HID / 8);

    // 1) QKV projection
    {
        dim3 grid(QKVD / GBN, TT / GBM);
        gemm_ps3<<<grid, 256, GEMM_SMEM>>>(hshi, hslo, wqhi, wqlo, qkv, TT, QKVD, HID);
    }
    // 2) fused RoPE + split to bf16 hi/lo (head-major)
    {
        int total = TT * (NH + 2 * NKV) * 64;
        rope_split<<<total / 256, 256>>>(qkv, qhi, qlo, khi, klo, vhi, vlo);
    }
    // 3) tensor-core causal GQA attention -> split bf16 output
    {
        dim3 grid(SEQ / AQ, NH, NB);
        attn_mma<<<grid, 256, ATT_SMEM>>>(qhi, qlo, khi, klo, vhi, vlo, atthi, attlo);
    }
    // 4) output projection
    {
        dim3 grid(HID / GBN, TT / GBM);
        gemm_ps3<<<grid, 256, GEMM_SMEM>>>(atthi, attlo, wohi, wolo, out, TT, HID, HID);
    }
}